// round 9
// baseline (speedup 1.0000x reference)
#include <cuda_runtime.h>
#include <cuda_bf16.h>
#include <math.h>
#include <stdint.h>

#define N_NODES 50000
#define N_EDGES 600000
#define NF      128
#define NG      512
#define NC      10
#define BN_EPS  1e-5f

// ---------------- scratch (device globals) ---------------------------------
__device__ int      g_deg   [N_NODES];
__device__ int      g_rowptr[N_NODES + 1];
__device__ int      g_cursor[N_NODES];
__device__ int      g_csrc  [N_EDGES];
__device__ float    g_dinv  [N_NODES];
__device__ float    g_y     [N_NODES * NF];
__device__ float    g_h     [N_NODES * NF];
__device__ unsigned g_gmax  [NG * NF];
__device__ float    g_g     [NG * NF];
__device__ float    g_m1    [NG * NF];
// B fragments for mma.sync m16n8k16, register order:
// [L(4)][kc(4)][s(2)][nt(16)][hl(2)][lane(32)][j(2)] as uint32 (bf16x2)
// one layer block = 16384 uint32 = 64KB, contiguous
__device__ unsigned g_bfrag[4 * 16384];

// ---------------- helpers --------------------------------------------------
__device__ __forceinline__ unsigned enc_f(float v) {
    unsigned u = __float_as_uint(v);
    return (u & 0x80000000u) ? ~u : (u | 0x80000000u);
}
__device__ __forceinline__ float dec_f(unsigned u) {
    return (u & 0x80000000u) ? __uint_as_float(u & 0x7FFFFFFFu)
                             : __uint_as_float(~u);
}

// ---------------- CSR build -------------------------------------------------
__global__ void zero_all() {
    int i = blockIdx.x * blockDim.x + threadIdx.x;
    if (i < N_NODES) g_deg[i] = 0;
    if (i < NG * NF) g_gmax[i] = 0u;
}
__global__ void deg_count(const int* __restrict__ dst) {
    int e = blockIdx.x * blockDim.x + threadIdx.x;
    if (e < N_EDGES) atomicAdd(&g_deg[dst[e]], 1);
}
__global__ __launch_bounds__(1024) void scan_deg() {
    __shared__ int sums[1024];
    const int CH = (N_NODES + 1023) / 1024;
    int t = threadIdx.x;
    int base = t * CH;
    int s = 0;
    for (int i = 0; i < CH; ++i) {
        int idx = base + i;
        if (idx < N_NODES) s += g_deg[idx];
    }
    sums[t] = s;
    __syncthreads();
    for (int off = 1; off < 1024; off <<= 1) {
        int v = 0;
        if (t >= off) v = sums[t - off];
        __syncthreads();
        if (t >= off) sums[t] += v;
        __syncthreads();
    }
    int run = (t == 0) ? 0 : sums[t - 1];
    for (int i = 0; i < CH; ++i) {
        int idx = base + i;
        if (idx < N_NODES) {
            g_rowptr[idx] = run;
            g_cursor[idx] = run;
            g_dinv[idx]   = rsqrtf((float)g_deg[idx] + 1.0f);
            run += g_deg[idx];
        }
    }
    if (t == 1023) g_rowptr[N_NODES] = run;
}
__global__ void csr_fill(const int* __restrict__ src, const int* __restrict__ dst) {
    int e = blockIdx.x * blockDim.x + threadIdx.x;
    if (e < N_EDGES) {
        int pos = atomicAdd(&g_cursor[dst[e]], 1);
        g_csrc[pos] = src[e];
    }
}

// ---------------- W pre-convert into mma B-fragment layout ------------------
__global__ void prep_w(const float* __restrict__ W1, const float* __restrict__ W2,
                       const float* __restrict__ W3, const float* __restrict__ LW1) {
    int i = blockIdx.x * blockDim.x + threadIdx.x;
    if (i >= 4 * NF * NF) return;
    int L = i >> 14;
    int r = i & 16383;
    int k = r >> 7;
    int n = r & 127;
    const float* W = (L == 0) ? W1 : (L == 1) ? W2 : (L == 2) ? W3 : LW1;
    float v = W[k * NF + n];
    __nv_bfloat16 hi = __float2bfloat16(v);
    __nv_bfloat16 lo = __float2bfloat16(v - __bfloat162float(hi));
    int kc = k >> 5;
    int s  = (k >> 4) & 1;
    int ko = k & 15;
    int nt = n >> 3;
    int lane = (n & 7) * 4 + ((ko & 7) >> 1);
    int j    = ko >> 3;
    int half = ko & 1;
    unsigned short* p = reinterpret_cast<unsigned short*>(g_bfrag);
    size_t bh = (((((size_t)((L * 4 + kc) * 2 + s) * 16 + nt) * 2 + 0) * 32 + lane) * 2 + j) * 2 + half;
    size_t bl = (((((size_t)((L * 4 + kc) * 2 + s) * 16 + nt) * 2 + 1) * 32 + lane) * 2 + j) * 2 + half;
    p[bh] = __bfloat16_as_ushort(hi);
    p[bl] = __bfloat16_as_ushort(lo);
}

// ---------------- mma.sync GEMM with smem-staged B fragments ---------------
#define ASTRIDE 20
// dynamic smem layout (uint32 units): AshH[2560] | AshL[2560] | Bst[16384]
#define GEMM_SMEM_BYTES ((2560 + 2560 + 16384) * 4)

__device__ __forceinline__ void mma_bf16(float* d, const unsigned* a, unsigned b0, unsigned b1) {
    asm volatile(
        "mma.sync.aligned.m16n8k16.row.col.f32.bf16.bf16.f32 "
        "{%0,%1,%2,%3}, {%4,%5,%6,%7}, {%8,%9}, {%0,%1,%2,%3};"
        : "+f"(d[0]), "+f"(d[1]), "+f"(d[2]), "+f"(d[3])
        : "r"(a[0]), "r"(a[1]), "r"(a[2]), "r"(a[3]), "r"(b0), "r"(b1));
}

__global__ __launch_bounds__(256)
void gemm_mma(const float* __restrict__ A, int L, float* __restrict__ out,
              const float* __restrict__ dinv, const float* __restrict__ bias,
              int nrows, int do_relu)
{
    extern __shared__ unsigned sh[];
    unsigned* AshH = sh;
    unsigned* AshL = sh + 2560;
    unsigned* Bst  = sh + 5120;

    const int tid   = threadIdx.x;
    const int warp  = tid >> 5;
    const int lane  = tid & 31;
    const int l4    = lane >> 2;
    const int lm    = lane & 3;
    const int mrowg = (warp & 3) * 32;
    const int ncolg = (warp >> 2) * 64;
    const int row0  = blockIdx.x * 128;

    // stage this layer's 64KB fragment block into smem (coalesced uint4)
    {
        const uint4* src = reinterpret_cast<const uint4*>(g_bfrag + L * 16384);
        uint4* dst = reinterpret_cast<uint4*>(Bst);
        #pragma unroll
        for (int it = 0; it < 16; ++it)
            dst[tid + it * 256] = src[tid + it * 256];
    }

    float d[2][8][4];
    #pragma unroll
    for (int mt = 0; mt < 2; ++mt)
        #pragma unroll
        for (int nt = 0; nt < 8; ++nt)
            #pragma unroll
            for (int q = 0; q < 4; ++q) d[mt][nt][q] = 0.f;

    const int arow  = tid >> 1;
    const int ahalf = tid & 1;

    for (int kc = 0; kc < 4; ++kc) {
        {
            int gr = row0 + arow;
            #pragma unroll
            for (int q = 0; q < 4; ++q) {
                float4 v = make_float4(0.f, 0.f, 0.f, 0.f);
                if (gr < nrows)
                    v = *reinterpret_cast<const float4*>(
                        &A[gr * NF + kc * 32 + ahalf * 16 + q * 4]);
                __nv_bfloat16 hx = __float2bfloat16(v.x);
                __nv_bfloat16 hy = __float2bfloat16(v.y);
                __nv_bfloat16 hz = __float2bfloat16(v.z);
                __nv_bfloat16 hw = __float2bfloat16(v.w);
                unsigned hp0 = ((unsigned)__bfloat16_as_ushort(hy) << 16) | __bfloat16_as_ushort(hx);
                unsigned hp1 = ((unsigned)__bfloat16_as_ushort(hw) << 16) | __bfloat16_as_ushort(hz);
                __nv_bfloat16 lx = __float2bfloat16(v.x - __bfloat162float(hx));
                __nv_bfloat16 ly = __float2bfloat16(v.y - __bfloat162float(hy));
                __nv_bfloat16 lz = __float2bfloat16(v.z - __bfloat162float(hz));
                __nv_bfloat16 lw = __float2bfloat16(v.w - __bfloat162float(hw));
                unsigned lp0 = ((unsigned)__bfloat16_as_ushort(ly) << 16) | __bfloat16_as_ushort(lx);
                unsigned lp1 = ((unsigned)__bfloat16_as_ushort(lw) << 16) | __bfloat16_as_ushort(lz);
                int p = ahalf * 8 + q * 2;
                AshH[arow * ASTRIDE + p + 0] = hp0;
                AshH[arow * ASTRIDE + p + 1] = hp1;
                AshL[arow * ASTRIDE + p + 0] = lp0;
                AshL[arow * ASTRIDE + p + 1] = lp1;
            }
        }
        __syncthreads();

        #pragma unroll
        for (int s = 0; s < 2; ++s) {
            unsigned aH[2][4], aL[2][4];
            #pragma unroll
            for (int mt = 0; mt < 2; ++mt) {
                int rbase = mrowg + mt * 16;
                int p0 = s * 8 + lm;
                aH[mt][0] = AshH[(rbase + l4)     * ASTRIDE + p0];
                aH[mt][1] = AshH[(rbase + l4 + 8) * ASTRIDE + p0];
                aH[mt][2] = AshH[(rbase + l4)     * ASTRIDE + p0 + 4];
                aH[mt][3] = AshH[(rbase + l4 + 8) * ASTRIDE + p0 + 4];
                aL[mt][0] = AshL[(rbase + l4)     * ASTRIDE + p0];
                aL[mt][1] = AshL[(rbase + l4 + 8) * ASTRIDE + p0];
                aL[mt][2] = AshL[(rbase + l4)     * ASTRIDE + p0 + 4];
                aL[mt][3] = AshL[(rbase + l4 + 8) * ASTRIDE + p0 + 4];
            }
            #pragma unroll
            for (int nt = 0; nt < 8; ++nt) {
                int ntg = (ncolg >> 3) + nt;
                int idx = (((kc * 2 + s) * 16 + ntg) * 2) * 64 + lane * 2;
                uint2 bH = *reinterpret_cast<const uint2*>(&Bst[idx]);
                uint2 bL = *reinterpret_cast<const uint2*>(&Bst[idx + 64]);
                #pragma unroll
                for (int mt = 0; mt < 2; ++mt) {
                    mma_bf16(d[mt][nt], aH[mt], bH.x, bH.y);
                    mma_bf16(d[mt][nt], aH[mt], bL.x, bL.y);
                    mma_bf16(d[mt][nt], aL[mt], bH.x, bH.y);
                }
            }
        }
        __syncthreads();
    }

    #pragma unroll
    for (int mt = 0; mt < 2; ++mt) {
        int r_lo = row0 + mrowg + mt * 16 + l4;
        int r_hi = r_lo + 8;
        float s_lo = 1.f, s_hi = 1.f;
        if (dinv) {
            if (r_lo < nrows) s_lo = dinv[r_lo];
            if (r_hi < nrows) s_hi = dinv[r_hi];
        }
        #pragma unroll
        for (int nt = 0; nt < 8; ++nt) {
            int col = ncolg + nt * 8 + lm * 2;
            float b0 = 0.f, b1 = 0.f;
            if (bias) { b0 = bias[col]; b1 = bias[col + 1]; }
            float2 v0 = make_float2(d[mt][nt][0] * s_lo + b0, d[mt][nt][1] * s_lo + b1);
            float2 v1 = make_float2(d[mt][nt][2] * s_hi + b0, d[mt][nt][3] * s_hi + b1);
            if (do_relu) {
                v0.x = fmaxf(v0.x, 0.f); v0.y = fmaxf(v0.y, 0.f);
                v1.x = fmaxf(v1.x, 0.f); v1.y = fmaxf(v1.y, 0.f);
            }
            if (r_lo < nrows)
                *reinterpret_cast<float2*>(&out[r_lo * NF + col]) = v0;
            if (r_hi < nrows)
                *reinterpret_cast<float2*>(&out[r_hi * NF + col]) = v1;
        }
    }
}

// ---------------- aggregate: 4 warps/node (32-feature quarters), 8-deep -----
// MODE 0: y pre-scaled by dinv:  h = relu(dinv*(sum + self) + bias)
// MODE 1: as 0, then BN(eval) + per-graph atomicMax (no h store)
// MODE 2: y UNscaled: h = relu(dinv*(sum_src dinv[s]*y[s] + dinv*self) + bias)
template <int MODE>
__global__ __launch_bounds__(256)
void aggregate(const float* __restrict__ y, const float* __restrict__ bias,
               float* __restrict__ h,
               const int* __restrict__ batch,
               const float* __restrict__ gamma, const float* __restrict__ beta,
               const float* __restrict__ rmean, const float* __restrict__ rvar)
{
    int w    = threadIdx.x >> 5;            // 0..7
    int node = blockIdx.x * 2 + (w >> 2);
    int q    = w & 3;
    int lane = threadIdx.x & 31;
    if (node >= N_NODES) return;

    int p0 = g_rowptr[node];
    int p1 = g_rowptr[node + 1];
    const int foff = q * 32 + lane;          // this warp's single-float slice

    float a = 0.f;
    int e = p0;
    for (; e + 8 <= p1; e += 8) {
        int s[8];
        #pragma unroll
        for (int i = 0; i < 8; ++i) s[i] = g_csrc[e + i];
        float v[8];
        #pragma unroll
        for (int i = 0; i < 8; ++i) v[i] = y[s[i] * NF + foff];
        if (MODE == 2) {
            float dd[8];
            #pragma unroll
            for (int i = 0; i < 8; ++i) dd[i] = g_dinv[s[i]];
            #pragma unroll
            for (int i = 0; i < 8; ++i) a += v[i] * dd[i];
        } else {
            #pragma unroll
            for (int i = 0; i < 8; ++i) a += v[i];
        }
    }
    for (; e < p1; ++e) {
        int s = g_csrc[e];
        float v = y[s * NF + foff];
        float ds = (MODE == 2) ? g_dinv[s] : 1.f;
        a += v * ds;
    }

    float self = y[node * NF + foff];
    float di   = g_dinv[node];
    float ss   = (MODE == 2) ? di : 1.f;
    float o = fmaxf(di * (a + self * ss) + bias[foff], 0.f);

    if (MODE != 1) {
        h[node * NF + foff] = o;
    } else {
        float v = (o - rmean[foff]) * rsqrtf(rvar[foff] + BN_EPS) * gamma[foff] + beta[foff];
        atomicMax(&g_gmax[batch[node] * NF + foff], enc_f(v));
    }
}

__global__ void decode_g() {
    int i = blockIdx.x * blockDim.x + threadIdx.x;
    if (i < NG * NF) g_g[i] = dec_f(g_gmax[i]);
}

// ---------------- fused MLP tail: m2 = relu(m1@lw2+lb2); out = m2@lw3+lb3 ---
__global__ __launch_bounds__(64)
void head_tail(const float* __restrict__ M1,
               const float* __restrict__ lw2, const float* __restrict__ lb2,
               const float* __restrict__ lw3, const float* __restrict__ lb3,
               float* __restrict__ out)
{
    __shared__ float xs[128];
    __shared__ float m2[64];
    int row = blockIdx.x;
    int t = threadIdx.x;
    xs[t]      = M1[row * 128 + t];
    xs[t + 64] = M1[row * 128 + t + 64];
    __syncthreads();
    {
        float s = lb2[t];
        #pragma unroll 8
        for (int k = 0; k < 128; ++k) s += xs[k] * lw2[k * 64 + t];
        m2[t] = fmaxf(s, 0.f);
    }
    __syncthreads();
    if (t < NC) {
        float s = lb3[t];
        #pragma unroll 8
        for (int k = 0; k < 64; ++k) s += m2[k] * lw3[k * NC + t];
        out[row * NC + t] = s;
    }
}

// ---------------- launch ---------------------------------------------------
extern "C" void kernel_launch(void* const* d_in, const int* in_sizes, int n_in,
                              void* d_out, int out_size)
{
    const float* x     = (const float*)d_in[0];
    const int*   ei    = (const int*)  d_in[1];
    const int*   batch = (const int*)  d_in[2];
    const float* W1 = (const float*)d_in[3];  const float* b1 = (const float*)d_in[4];
    const float* W2 = (const float*)d_in[5];  const float* b2 = (const float*)d_in[6];
    const float* W3 = (const float*)d_in[7];  const float* b3 = (const float*)d_in[8];
    const float* gamma = (const float*)d_in[9];
    const float* beta  = (const float*)d_in[10];
    const float* rmean = (const float*)d_in[11];
    const float* rvar  = (const float*)d_in[12];
    const float* lw1 = (const float*)d_in[13]; const float* lb1 = (const float*)d_in[14];
    const float* lw2 = (const float*)d_in[15]; const float* lb2 = (const float*)d_in[16];
    const float* lw3 = (const float*)d_in[17]; const float* lb3 = (const float*)d_in[18];
    float* out = (float*)d_out;

    const int* src = ei;
    const int* dst = ei + N_EDGES;

    void *p_dinv, *p_y, *p_h, *p_g, *p_m1;
    cudaGetSymbolAddress(&p_dinv, g_dinv);
    cudaGetSymbolAddress(&p_y,    g_y);
    cudaGetSymbolAddress(&p_h,    g_h);
    cudaGetSymbolAddress(&p_g,    g_g);
    cudaGetSymbolAddress(&p_m1,   g_m1);
    float* y = (float*)p_y;
    float* h = (float*)p_h;
    const float* dinv = (const float*)p_dinv;

    cudaFuncSetAttribute(gemm_mma, cudaFuncAttributeMaxDynamicSharedMemorySize,
                         GEMM_SMEM_BYTES);

    const int EB = (N_EDGES + 255) / 256;
    const int ZB = (((N_NODES > NG * NF) ? N_NODES : NG * NF) + 255) / 256;
    const int GRID_GEMM = (N_NODES + 127) / 128;
    const int GRID_AGG  = (N_NODES + 1) / 2;

    // ---- fork: CSR build chain on a side stream, concurrent with gemm1 ----
    cudaStream_t s2;
    cudaEvent_t evA, evB;
    cudaStreamCreateWithFlags(&s2, cudaStreamNonBlocking);
    cudaEventCreateWithFlags(&evA, cudaEventDisableTiming);
    cudaEventCreateWithFlags(&evB, cudaEventDisableTiming);

    cudaEventRecord(evA, 0);
    cudaStreamWaitEvent(s2, evA, 0);
    zero_all<<<ZB, 256, 0, s2>>>();
    deg_count<<<EB, 256, 0, s2>>>(dst);
    scan_deg<<<1, 1024, 0, s2>>>();
    csr_fill<<<EB, 256, 0, s2>>>(src, dst);
    cudaEventRecord(evB, s2);

    // ---- main stream: weights + layer-1 GEMM (no dinv dependency) ----
    prep_w<<<(4 * NF * NF + 255) / 256, 256>>>(W1, W2, W3, lw1);
    gemm_mma<<<GRID_GEMM, 256, GEMM_SMEM_BYTES>>>(x, 0, y, nullptr, nullptr, N_NODES, 0);

    // join CSR chain, then proceed
    cudaStreamWaitEvent(0, evB, 0);

    // layer 1 (aggregate applies dinv[src] itself)
    aggregate<2><<<GRID_AGG, 256>>>(y, b1, h, nullptr, nullptr, nullptr, nullptr, nullptr);
    // layer 2
    gemm_mma<<<GRID_GEMM, 256, GEMM_SMEM_BYTES>>>(h, 1, y, dinv, nullptr, N_NODES, 0);
    aggregate<0><<<GRID_AGG, 256>>>(y, b2, h, nullptr, nullptr, nullptr, nullptr, nullptr);
    // layer 3 + BN + pool
    gemm_mma<<<GRID_GEMM, 256, GEMM_SMEM_BYTES>>>(h, 2, y, dinv, nullptr, N_NODES, 0);
    aggregate<1><<<GRID_AGG, 256>>>(y, b3, nullptr, batch, gamma, beta, rmean, rvar);

    decode_g<<<(NG * NF + 255) / 256, 256>>>();

    // MLP head
    gemm_mma<<<(NG + 127) / 128, 256, GEMM_SMEM_BYTES>>>((const float*)p_g, 3, (float*)p_m1,
                                                         nullptr, lb1, NG, 1);
    head_tail<<<NG, 64>>>((const float*)p_m1, lw2, lb2, lw3, lb3, out);
}

// round 10
// speedup vs baseline: 1.2814x; 1.2814x over previous
#include <cuda_runtime.h>
#include <cuda_bf16.h>
#include <math.h>
#include <stdint.h>

#define N_NODES 50000
#define N_EDGES 600000
#define NF      128
#define NG      512
#define NC      10
#define BN_EPS  1e-5f

// ---------------- scratch (device globals) ---------------------------------
__device__ int      g_deg   [N_NODES];
__device__ int      g_rowptr[N_NODES + 1];
__device__ int      g_cursor[N_NODES];
__device__ int      g_csrc  [N_EDGES];
__device__ float    g_dinv  [N_NODES];
__device__ float    g_y     [N_NODES * NF];
__device__ float    g_h     [N_NODES * NF];
__device__ unsigned g_gmax  [NG * NF];
__device__ float    g_g     [NG * NF];
__device__ float    g_m1    [NG * NF];
// B fragments for mma.sync m16n8k16, register order:
// [L(4)][kc(4)][s(2)][nt(16)][hl(2)][lane(32)][j(2)] as uint32 (bf16x2)
__device__ unsigned g_bfrag[4 * 16384];

// ---------------- helpers --------------------------------------------------
__device__ __forceinline__ unsigned enc_f(float v) {
    unsigned u = __float_as_uint(v);
    return (u & 0x80000000u) ? ~u : (u | 0x80000000u);
}
__device__ __forceinline__ float dec_f(unsigned u) {
    return (u & 0x80000000u) ? __uint_as_float(u & 0x7FFFFFFFu)
                             : __uint_as_float(~u);
}

// ---------------- CSR build -------------------------------------------------
__global__ void zero_all() {
    int i = blockIdx.x * blockDim.x + threadIdx.x;
    if (i < N_NODES) g_deg[i] = 0;
    if (i < NG * NF) g_gmax[i] = 0u;
}
__global__ void deg_count(const int* __restrict__ dst) {
    int e = blockIdx.x * blockDim.x + threadIdx.x;
    if (e < N_EDGES) atomicAdd(&g_deg[dst[e]], 1);
}
__global__ __launch_bounds__(1024) void scan_deg() {
    __shared__ int sums[1024];
    const int CH = (N_NODES + 1023) / 1024;
    int t = threadIdx.x;
    int base = t * CH;
    int s = 0;
    for (int i = 0; i < CH; ++i) {
        int idx = base + i;
        if (idx < N_NODES) s += g_deg[idx];
    }
    sums[t] = s;
    __syncthreads();
    for (int off = 1; off < 1024; off <<= 1) {
        int v = 0;
        if (t >= off) v = sums[t - off];
        __syncthreads();
        if (t >= off) sums[t] += v;
        __syncthreads();
    }
    int run = (t == 0) ? 0 : sums[t - 1];
    for (int i = 0; i < CH; ++i) {
        int idx = base + i;
        if (idx < N_NODES) {
            g_rowptr[idx] = run;
            g_cursor[idx] = run;
            g_dinv[idx]   = rsqrtf((float)g_deg[idx] + 1.0f);
            run += g_deg[idx];
        }
    }
    if (t == 1023) g_rowptr[N_NODES] = run;
}
__global__ void csr_fill(const int* __restrict__ src, const int* __restrict__ dst) {
    int e = blockIdx.x * blockDim.x + threadIdx.x;
    if (e < N_EDGES) {
        int pos = atomicAdd(&g_cursor[dst[e]], 1);
        g_csrc[pos] = src[e];
    }
}

// ---------------- W pre-convert into mma B-fragment layout ------------------
__global__ void prep_w(const float* __restrict__ W1, const float* __restrict__ W2,
                       const float* __restrict__ W3, const float* __restrict__ LW1) {
    int i = blockIdx.x * blockDim.x + threadIdx.x;
    if (i >= 4 * NF * NF) return;
    int L = i >> 14;
    int r = i & 16383;
    int k = r >> 7;
    int n = r & 127;
    const float* W = (L == 0) ? W1 : (L == 1) ? W2 : (L == 2) ? W3 : LW1;
    float v = W[k * NF + n];
    __nv_bfloat16 hi = __float2bfloat16(v);
    __nv_bfloat16 lo = __float2bfloat16(v - __bfloat162float(hi));
    int kc = k >> 5;
    int s  = (k >> 4) & 1;
    int ko = k & 15;
    int nt = n >> 3;
    int lane = (n & 7) * 4 + ((ko & 7) >> 1);
    int j    = ko >> 3;
    int half = ko & 1;
    unsigned short* p = reinterpret_cast<unsigned short*>(g_bfrag);
    size_t bh = (((((size_t)((L * 4 + kc) * 2 + s) * 16 + nt) * 2 + 0) * 32 + lane) * 2 + j) * 2 + half;
    size_t bl = (((((size_t)((L * 4 + kc) * 2 + s) * 16 + nt) * 2 + 1) * 32 + lane) * 2 + j) * 2 + half;
    p[bh] = __bfloat16_as_ushort(hi);
    p[bl] = __bfloat16_as_ushort(lo);
}

// ---------------- mma.sync GEMM: out = (A @ W_L) [* dinv] [+bias][relu] -----
// 128x128 CTA tile, 8 warps x (32 rows x 64 cols), K chunks of 32,
// bf16 hi/lo 3-pass split, fp32 accumulate.  (R5/R8 version.)
#define ASTRIDE 20

__device__ __forceinline__ void mma_bf16(float* d, const unsigned* a, unsigned b0, unsigned b1) {
    asm volatile(
        "mma.sync.aligned.m16n8k16.row.col.f32.bf16.bf16.f32 "
        "{%0,%1,%2,%3}, {%4,%5,%6,%7}, {%8,%9}, {%0,%1,%2,%3};"
        : "+f"(d[0]), "+f"(d[1]), "+f"(d[2]), "+f"(d[3])
        : "r"(a[0]), "r"(a[1]), "r"(a[2]), "r"(a[3]), "r"(b0), "r"(b1));
}

__global__ __launch_bounds__(256)
void gemm_mma(const float* __restrict__ A, int L, float* __restrict__ out,
              const float* __restrict__ dinv, const float* __restrict__ bias,
              int nrows, int do_relu)
{
    __shared__ unsigned AshH[128 * ASTRIDE];
    __shared__ unsigned AshL[128 * ASTRIDE];

    const int tid   = threadIdx.x;
    const int warp  = tid >> 5;
    const int lane  = tid & 31;
    const int l4    = lane >> 2;
    const int lm    = lane & 3;
    const int mrowg = (warp & 3) * 32;
    const int ncolg = (warp >> 2) * 64;
    const int row0  = blockIdx.x * 128;

    float d[2][8][4];
    #pragma unroll
    for (int mt = 0; mt < 2; ++mt)
        #pragma unroll
        for (int nt = 0; nt < 8; ++nt)
            #pragma unroll
            for (int q = 0; q < 4; ++q) d[mt][nt][q] = 0.f;

    const int arow  = tid >> 1;
    const int ahalf = tid & 1;

    for (int kc = 0; kc < 4; ++kc) {
        {
            int gr = row0 + arow;
            #pragma unroll
            for (int q = 0; q < 4; ++q) {
                float4 v = make_float4(0.f, 0.f, 0.f, 0.f);
                if (gr < nrows)
                    v = *reinterpret_cast<const float4*>(
                        &A[gr * NF + kc * 32 + ahalf * 16 + q * 4]);
                __nv_bfloat16 hx = __float2bfloat16(v.x);
                __nv_bfloat16 hy = __float2bfloat16(v.y);
                __nv_bfloat16 hz = __float2bfloat16(v.z);
                __nv_bfloat16 hw = __float2bfloat16(v.w);
                unsigned hp0 = ((unsigned)__bfloat16_as_ushort(hy) << 16) | __bfloat16_as_ushort(hx);
                unsigned hp1 = ((unsigned)__bfloat16_as_ushort(hw) << 16) | __bfloat16_as_ushort(hz);
                __nv_bfloat16 lx = __float2bfloat16(v.x - __bfloat162float(hx));
                __nv_bfloat16 ly = __float2bfloat16(v.y - __bfloat162float(hy));
                __nv_bfloat16 lz = __float2bfloat16(v.z - __bfloat162float(hz));
                __nv_bfloat16 lw = __float2bfloat16(v.w - __bfloat162float(hw));
                unsigned lp0 = ((unsigned)__bfloat16_as_ushort(ly) << 16) | __bfloat16_as_ushort(lx);
                unsigned lp1 = ((unsigned)__bfloat16_as_ushort(lw) << 16) | __bfloat16_as_ushort(lz);
                int p = ahalf * 8 + q * 2;
                AshH[arow * ASTRIDE + p + 0] = hp0;
                AshH[arow * ASTRIDE + p + 1] = hp1;
                AshL[arow * ASTRIDE + p + 0] = lp0;
                AshL[arow * ASTRIDE + p + 1] = lp1;
            }
        }
        __syncthreads();

        #pragma unroll
        for (int s = 0; s < 2; ++s) {
            unsigned aH[2][4], aL[2][4];
            #pragma unroll
            for (int mt = 0; mt < 2; ++mt) {
                int rbase = mrowg + mt * 16;
                int p0 = s * 8 + lm;
                aH[mt][0] = AshH[(rbase + l4)     * ASTRIDE + p0];
                aH[mt][1] = AshH[(rbase + l4 + 8) * ASTRIDE + p0];
                aH[mt][2] = AshH[(rbase + l4)     * ASTRIDE + p0 + 4];
                aH[mt][3] = AshH[(rbase + l4 + 8) * ASTRIDE + p0 + 4];
                aL[mt][0] = AshL[(rbase + l4)     * ASTRIDE + p0];
                aL[mt][1] = AshL[(rbase + l4 + 8) * ASTRIDE + p0];
                aL[mt][2] = AshL[(rbase + l4)     * ASTRIDE + p0 + 4];
                aL[mt][3] = AshL[(rbase + l4 + 8) * ASTRIDE + p0 + 4];
            }
            #pragma unroll
            for (int nt = 0; nt < 8; ++nt) {
                int ntg = (ncolg >> 3) + nt;
                size_t idx = (((size_t)((L * 4 + kc) * 2 + s) * 16 + ntg) * 2) * 64 + lane * 2;
                uint2 bH = *reinterpret_cast<const uint2*>(&g_bfrag[idx]);
                uint2 bL = *reinterpret_cast<const uint2*>(&g_bfrag[idx + 64]);
                #pragma unroll
                for (int mt = 0; mt < 2; ++mt) {
                    mma_bf16(d[mt][nt], aH[mt], bH.x, bH.y);
                    mma_bf16(d[mt][nt], aH[mt], bL.x, bL.y);
                    mma_bf16(d[mt][nt], aL[mt], bH.x, bH.y);
                }
            }
        }
        __syncthreads();
    }

    #pragma unroll
    for (int mt = 0; mt < 2; ++mt) {
        int r_lo = row0 + mrowg + mt * 16 + l4;
        int r_hi = r_lo + 8;
        float s_lo = 1.f, s_hi = 1.f;
        if (dinv) {
            if (r_lo < nrows) s_lo = dinv[r_lo];
            if (r_hi < nrows) s_hi = dinv[r_hi];
        }
        #pragma unroll
        for (int nt = 0; nt < 8; ++nt) {
            int col = ncolg + nt * 8 + lm * 2;
            float b0 = 0.f, b1 = 0.f;
            if (bias) { b0 = bias[col]; b1 = bias[col + 1]; }
            float2 v0 = make_float2(d[mt][nt][0] * s_lo + b0, d[mt][nt][1] * s_lo + b1);
            float2 v1 = make_float2(d[mt][nt][2] * s_hi + b0, d[mt][nt][3] * s_hi + b1);
            if (do_relu) {
                v0.x = fmaxf(v0.x, 0.f); v0.y = fmaxf(v0.y, 0.f);
                v1.x = fmaxf(v1.x, 0.f); v1.y = fmaxf(v1.y, 0.f);
            }
            if (r_lo < nrows)
                *reinterpret_cast<float2*>(&out[r_lo * NF + col]) = v0;
            if (r_hi < nrows)
                *reinterpret_cast<float2*>(&out[r_hi * NF + col]) = v1;
        }
    }
}

// ---------------- aggregate: 2 warps/node (64-feature halves), 8-deep ILP ---
// MODE 0: y pre-scaled by dinv:  h = relu(dinv*(sum + self) + bias)
// MODE 1: as 0, then BN(eval) + per-graph atomicMax (no h store)
// MODE 2: y UNscaled: h = relu(dinv*(sum_src dinv[s]*y[s] + dinv*self) + bias)
template <int MODE>
__global__ __launch_bounds__(256)
void aggregate(const float* __restrict__ y, const float* __restrict__ bias,
               float* __restrict__ h,
               const int* __restrict__ batch,
               const float* __restrict__ gamma, const float* __restrict__ beta,
               const float* __restrict__ rmean, const float* __restrict__ rvar)
{
    int w    = threadIdx.x >> 5;            // 0..7
    int node = blockIdx.x * 4 + (w >> 1);
    int half = w & 1;
    int lane = threadIdx.x & 31;
    if (node >= N_NODES) return;

    int p0 = g_rowptr[node];
    int p1 = g_rowptr[node + 1];
    const int foff = half * 64 + lane * 2;   // this warp's 2-float slice

    float2 a = make_float2(0.f, 0.f);
    int e = p0;
    for (; e + 8 <= p1; e += 8) {
        int s[8];
        #pragma unroll
        for (int i = 0; i < 8; ++i) s[i] = g_csrc[e + i];
        float2 v[8];
        #pragma unroll
        for (int i = 0; i < 8; ++i)
            v[i] = *reinterpret_cast<const float2*>(&y[s[i] * NF + foff]);
        if (MODE == 2) {
            float dd[8];
            #pragma unroll
            for (int i = 0; i < 8; ++i) dd[i] = g_dinv[s[i]];
            #pragma unroll
            for (int i = 0; i < 8; ++i) { a.x += v[i].x * dd[i]; a.y += v[i].y * dd[i]; }
        } else {
            #pragma unroll
            for (int i = 0; i < 8; ++i) { a.x += v[i].x; a.y += v[i].y; }
        }
    }
    for (; e < p1; ++e) {
        int s = g_csrc[e];
        float2 v = *reinterpret_cast<const float2*>(&y[s * NF + foff]);
        float ds = (MODE == 2) ? g_dinv[s] : 1.f;
        a.x += v.x * ds; a.y += v.y * ds;
    }

    float2 self = *reinterpret_cast<const float2*>(&y[node * NF + foff]);
    float  di   = g_dinv[node];
    float  ss   = (MODE == 2) ? di : 1.f;
    float2 bv   = *reinterpret_cast<const float2*>(&bias[foff]);
    float2 o;
    o.x = fmaxf(di * (a.x + self.x * ss) + bv.x, 0.f);
    o.y = fmaxf(di * (a.y + self.y * ss) + bv.y, 0.f);

    if (MODE != 1) {
        *reinterpret_cast<float2*>(&h[node * NF + foff]) = o;
    } else {
        float2 gm = *reinterpret_cast<const float2*>(&gamma[foff]);
        float2 bt = *reinterpret_cast<const float2*>(&beta[foff]);
        float2 mu = *reinterpret_cast<const float2*>(&rmean[foff]);
        float2 va = *reinterpret_cast<const float2*>(&rvar[foff]);
        float vx = (o.x - mu.x) * rsqrtf(va.x + BN_EPS) * gm.x + bt.x;
        float vy = (o.y - mu.y) * rsqrtf(va.y + BN_EPS) * gm.y + bt.y;
        unsigned* p = &g_gmax[batch[node] * NF + foff];
        atomicMax(p + 0, enc_f(vx));
        atomicMax(p + 1, enc_f(vy));
    }
}

__global__ void decode_g() {
    int i = blockIdx.x * blockDim.x + threadIdx.x;
    if (i < NG * NF) g_g[i] = dec_f(g_gmax[i]);
}

// ---------------- fused MLP tail: m2 = relu(m1@lw2+lb2); out = m2@lw3+lb3 ---
__global__ __launch_bounds__(64)
void head_tail(const float* __restrict__ M1,
               const float* __restrict__ lw2, const float* __restrict__ lb2,
               const float* __restrict__ lw3, const float* __restrict__ lb3,
               float* __restrict__ out)
{
    __shared__ float xs[128];
    __shared__ float m2[64];
    int row = blockIdx.x;
    int t = threadIdx.x;
    xs[t]      = M1[row * 128 + t];
    xs[t + 64] = M1[row * 128 + t + 64];
    __syncthreads();
    {
        float s = lb2[t];
        #pragma unroll 8
        for (int k = 0; k < 128; ++k) s += xs[k] * lw2[k * 64 + t];
        m2[t] = fmaxf(s, 0.f);
    }
    __syncthreads();
    if (t < NC) {
        float s = lb3[t];
        #pragma unroll 8
        for (int k = 0; k < 64; ++k) s += m2[k] * lw3[k * NC + t];
        out[row * NC + t] = s;
    }
}

// ---------------- launch ---------------------------------------------------
extern "C" void kernel_launch(void* const* d_in, const int* in_sizes, int n_in,
                              void* d_out, int out_size)
{
    const float* x     = (const float*)d_in[0];
    const int*   ei    = (const int*)  d_in[1];
    const int*   batch = (const int*)  d_in[2];
    const float* W1 = (const float*)d_in[3];  const float* b1 = (const float*)d_in[4];
    const float* W2 = (const float*)d_in[5];  const float* b2 = (const float*)d_in[6];
    const float* W3 = (const float*)d_in[7];  const float* b3 = (const float*)d_in[8];
    const float* gamma = (const float*)d_in[9];
    const float* beta  = (const float*)d_in[10];
    const float* rmean = (const float*)d_in[11];
    const float* rvar  = (const float*)d_in[12];
    const float* lw1 = (const float*)d_in[13]; const float* lb1 = (const float*)d_in[14];
    const float* lw2 = (const float*)d_in[15]; const float* lb2 = (const float*)d_in[16];
    const float* lw3 = (const float*)d_in[17]; const float* lb3 = (const float*)d_in[18];
    float* out = (float*)d_out;

    const int* src = ei;
    const int* dst = ei + N_EDGES;

    void *p_dinv, *p_y, *p_h, *p_g, *p_m1;
    cudaGetSymbolAddress(&p_dinv, g_dinv);
    cudaGetSymbolAddress(&p_y,    g_y);
    cudaGetSymbolAddress(&p_h,    g_h);
    cudaGetSymbolAddress(&p_g,    g_g);
    cudaGetSymbolAddress(&p_m1,   g_m1);
    float* y = (float*)p_y;
    float* h = (float*)p_h;
    const float* dinv = (const float*)p_dinv;

    const int EB = (N_EDGES + 255) / 256;
    const int ZB = (((N_NODES > NG * NF) ? N_NODES : NG * NF) + 255) / 256;
    const int GRID_GEMM = (N_NODES + 127) / 128;
    const int GRID_AGG  = (N_NODES + 3) / 4;

    // ---- fork: CSR build chain on a side stream, concurrent with gemm1 ----
    cudaStream_t s2;
    cudaEvent_t evA, evB;
    cudaStreamCreateWithFlags(&s2, cudaStreamNonBlocking);
    cudaEventCreateWithFlags(&evA, cudaEventDisableTiming);
    cudaEventCreateWithFlags(&evB, cudaEventDisableTiming);

    cudaEventRecord(evA, 0);
    cudaStreamWaitEvent(s2, evA, 0);
    zero_all<<<ZB, 256, 0, s2>>>();
    deg_count<<<EB, 256, 0, s2>>>(dst);
    scan_deg<<<1, 1024, 0, s2>>>();
    csr_fill<<<EB, 256, 0, s2>>>(src, dst);
    cudaEventRecord(evB, s2);

    // ---- main stream: weights + layer-1 GEMM (no dinv dependency) ----
    prep_w<<<(4 * NF * NF + 255) / 256, 256>>>(W1, W2, W3, lw1);
    gemm_mma<<<GRID_GEMM, 256>>>(x, 0, y, nullptr, nullptr, N_NODES, 0);

    // join CSR chain, then proceed
    cudaStreamWaitEvent(0, evB, 0);

    // layer 1 (aggregate applies dinv[src] itself)
    aggregate<2><<<GRID_AGG, 256>>>(y, b1, h, nullptr, nullptr, nullptr, nullptr, nullptr);
    // layer 2
    gemm_mma<<<GRID_GEMM, 256>>>(h, 1, y, dinv, nullptr, N_NODES, 0);
    aggregate<0><<<GRID_AGG, 256>>>(y, b2, h, nullptr, nullptr, nullptr, nullptr, nullptr);
    // layer 3 + BN + pool
    gemm_mma<<<GRID_GEMM, 256>>>(h, 2, y, dinv, nullptr, N_NODES, 0);
    aggregate<1><<<GRID_AGG, 256>>>(y, b3, nullptr, batch, gamma, beta, rmean, rvar);

    decode_g<<<(NG * NF + 255) / 256, 256>>>();

    // MLP head
    gemm_mma<<<(NG + 127) / 128, 256>>>((const float*)p_g, 3, (float*)p_m1,
                                        nullptr, lb1, NG, 1);
    head_tail<<<NG, 64>>>((const float*)p_m1, lw2, lb2, lw3, lb3, out);
}